// round 12
// baseline (speedup 1.0000x reference)
#include <cuda_runtime.h>
#include <cuda_fp16.h>
#include <math.h>
#include <stdint.h>

#define BATCH   4096
#define NROWS   8192
#define DIM     512
#define TAU_INV 10.0f

// Gram tiling
#define TM 128
#define TN 128
#define KC 32                 // k-chunk (2 k16 slices)
#define NCHUNKS (DIM / KC)    // 16
#define NTILE   (NROWS / TN)  // 64
#define NBLOCKS (NTILE * (NTILE + 1) / 2)   // 2080 upper-triangle tiles
#define NSTAGES 4

// SMEM layout: padded rows (16 fp16 data + 8 fp16 pad = 48B) for conflict-free ldmatrix
#define ROWB   48
#define SLICEB (128 * ROWB)           // 6144
#define MATB   (2 * SLICEB)           // 12288 (2 k16 slices)
#define OFF_A  0
#define OFF_B  MATB
#define STAGEB (2 * MATB)             // 24576
#define SMEM_TOTAL (NSTAGES * STAGEB) // 98304 (2 CTAs/SM = 196KB, proven to fit)

// ---------------------------------------------------------------------------
// Scratch (device globals: no runtime allocation)
__device__ __half        d_Xh[(size_t)NROWS * DIM];   // 8 MB (L2-resident)
__device__ float         d_gsum[NROWS];
__device__ unsigned int  d_gmax[NROWS];
__device__ float         d_gd[NROWS];

// ---------------------------------------------------------------------------
__device__ __forceinline__ uint32_t smem_to_u32(const void* p) {
    uint32_t a;
    asm("{ .reg .u64 t; cvta.to.shared.u64 t, %1; cvt.u32.u64 %0, t; }"
        : "=r"(a) : "l"(p));
    return a;
}

__device__ __forceinline__ void cp_async16(uint32_t dst, const void* src) {
    asm volatile("cp.async.cg.shared.global [%0], [%1], 16;"
                 :: "r"(dst), "l"(src) : "memory");
}
__device__ __forceinline__ void cp_commit() {
    asm volatile("cp.async.commit_group;" ::: "memory");
}
template <int N>
__device__ __forceinline__ void cp_wait() {
    asm volatile("cp.async.wait_group %0;" :: "n"(N) : "memory");
}

__device__ __forceinline__ void ldsm4(uint32_t* r, uint32_t addr) {
    asm volatile("ldmatrix.sync.aligned.m8n8.x4.shared.b16 {%0,%1,%2,%3}, [%4];"
                 : "=r"(r[0]), "=r"(r[1]), "=r"(r[2]), "=r"(r[3]) : "r"(addr));
}

__device__ __forceinline__ void mma16816(float* d, const uint32_t* a,
                                         uint32_t b0, uint32_t b1) {
    asm volatile(
        "mma.sync.aligned.m16n8k16.row.col.f32.f16.f16.f32 "
        "{%0,%1,%2,%3}, {%4,%5,%6,%7}, {%8,%9}, {%0,%1,%2,%3};\n"
        : "+f"(d[0]), "+f"(d[1]), "+f"(d[2]), "+f"(d[3])
        : "r"(a[0]), "r"(a[1]), "r"(a[2]), "r"(a[3]), "r"(b0), "r"(b1));
}

// Order-preserving float<->uint encoding for atomicMax on float
__device__ __forceinline__ unsigned int fenc(float f) {
    unsigned int u = __float_as_uint(f);
    return (u & 0x80000000u) ? ~u : (u | 0x80000000u);
}
__device__ __forceinline__ float fdec(unsigned int u) {
    u = (u & 0x80000000u) ? (u & 0x7FFFFFFFu) : ~u;
    return __uint_as_float(u);
}

// ---------------------------------------------------------------------------
// Normalize rows -> fp16, warp-per-row (MLP=4, warp-local reduction only).
// Also zeroes the row's accumulators (fused zero).
__global__ __launch_bounds__(256) void norm_kernel(const float* __restrict__ a,
                                                   const float* __restrict__ b) {
    int lane = threadIdx.x & 31;
    int r = blockIdx.x * 8 + (threadIdx.x >> 5);
    const float* src = (r < BATCH) ? a + (size_t)r * DIM
                                   : b + (size_t)(r - BATCH) * DIM;

    if (lane == 0) {
        d_gsum[r] = 0.0f;
        d_gmax[r] = 0u;
        d_gd[r]   = 0.0f;
    }

    // 4 independent float4 loads per lane (coalesced, MLP=4)
    float4 v[4];
    #pragma unroll
    for (int i = 0; i < 4; i++)
        v[i] = reinterpret_cast<const float4*>(src)[lane + 32 * i];

    float ss = 0.0f;
    #pragma unroll
    for (int i = 0; i < 4; i++)
        ss += v[i].x * v[i].x + v[i].y * v[i].y + v[i].z * v[i].z + v[i].w * v[i].w;
    #pragma unroll
    for (int o = 16; o > 0; o >>= 1) ss += __shfl_xor_sync(0xffffffffu, ss, o);

    float scale = 1.0f / fmaxf(sqrtf(ss), 1e-12f);

    uint2* dh = reinterpret_cast<uint2*>(d_Xh + (size_t)r * DIM);
    #pragma unroll
    for (int i = 0; i < 4; i++) {
        __half2 h0 = __floats2half2_rn(v[i].x * scale, v[i].y * scale);
        __half2 h1 = __floats2half2_rn(v[i].z * scale, v[i].w * scale);
        uint2 pk;
        pk.x = *reinterpret_cast<uint32_t*>(&h0);
        pk.y = *reinterpret_cast<uint32_t*>(&h1);
        dh[lane + 32 * i] = pk;
    }
}

// ---------------------------------------------------------------------------
// Gram kernel over the UPPER TRIANGLE of the 64x64 tile grid, single fp16
// MMA chain (fp32 accum), KC=32 with a 4-stage cp.async ring (prefetch
// distance 3, one barrier per chunk). Off-diagonal tile (bi < bj): row-scan
// feeds rows i0.., per-COLUMN reduction feeds rows j0.. (G symmetric).
// Diagonal tile: row-scan only, self excluded. Partner tiles (bj == bi^32):
// local diagonal yields d_gd for both rows.
__global__ __launch_bounds__(256, 2) void gram_kernel() {
    extern __shared__ __align__(1024) unsigned char smem[];
    uint32_t sbase = smem_to_u32(smem);

    const int tid  = threadIdx.x;
    const int lane = tid & 31;
    const int wid  = tid >> 5;
    const int wy   = wid & 3;    // M warp (4)
    const int wx   = wid >> 2;   // N warp (2)

    // Linear block id -> (bi, bj) with bi <= bj
    int t = blockIdx.x;
    int bi = (int)((129.0f - sqrtf(16641.0f - 8.0f * (float)t)) * 0.5f);
    if (bi < 0) bi = 0;
    if (bi > NTILE - 1) bi = NTILE - 1;
    while (bi > 0 && bi * NTILE - bi * (bi - 1) / 2 > t) bi--;
    while ((bi + 1) * NTILE - (bi + 1) * bi / 2 <= t) bi++;
    int bj = bi + (t - (bi * NTILE - bi * (bi - 1) / 2));

    const int i0 = bi * TM;
    const int j0 = bj * TN;
    const bool diag = (bi == bj);
    const bool part = (bj == (bi ^ (BATCH / TN)));   // bi<32, bj=bi+32

    float c[2][8][4];
    #pragma unroll
    for (int mt = 0; mt < 2; mt++)
        #pragma unroll
        for (int nt = 0; nt < 8; nt++)
            #pragma unroll
            for (int q = 0; q < 4; q++) c[mt][nt][q] = 0.0f;

    // cp.async loader: one stage = 1024 16B chunks, 4 per thread.
    // idx bits: h=bit0, r=bits1..7, s=bit8, m=bit9 (0=A rows i0.., 1=B rows j0..)
    auto load_stage = [&](int st, int k0) {
        #pragma unroll
        for (int it = 0; it < 4; it++) {
            int idx = tid + it * 256;
            int h = idx & 1;
            int r = (idx >> 1) & 127;
            int s = (idx >> 8) & 1;
            int m = idx >> 9;
            int rowbase = m ? j0 : i0;
            const __half* g =
                d_Xh + (size_t)(rowbase + r) * DIM + k0 + s * 16 + h * 8;
            uint32_t dst = sbase + st * STAGEB + (m ? OFF_B : OFF_A) +
                           s * SLICEB + r * ROWB + h * 16;
            cp_async16(dst, g);
        }
        cp_commit();
    };

    const uint32_t laneoff =
        (uint32_t)(((lane & 7) + ((lane >> 3) & 1) * 8) * ROWB + (lane >> 4) * 16);

    // Prologue: three chunks in flight
    load_stage(0, 0);
    load_stage(1, KC);
    load_stage(2, 2 * KC);

    for (int ch = 0; ch < NCHUNKS; ch++) {
        // Drain until chunk ch has landed. Issued so far = min(ch+3, NCHUNKS);
        // allowable pending = min(2, NCHUNKS-1-ch).
        if (ch + 3 <= NCHUNKS)      cp_wait<2>();
        else if (ch + 2 <= NCHUNKS) cp_wait<1>();
        else                        cp_wait<0>();
        __syncthreads();   // compute of ch-1 done everywhere; stage ch visible

        // Prefetch ch+3 into stage (ch+3)%4 == (ch-1)%4 (consumer confirmed done)
        if (ch + 3 < NCHUNKS) load_stage((ch + 3) & 3, (ch + 3) * KC);

        uint32_t sb = sbase + (ch & 3) * STAGEB;
        #pragma unroll
        for (int s = 0; s < 2; s++) {
            uint32_t slice = sb + s * SLICEB;
            uint32_t aa[2][4], bb[4][4];
            #pragma unroll
            for (int mt = 0; mt < 2; mt++) {
                uint32_t arow = (uint32_t)((wy * 32 + mt * 16) * ROWB) + laneoff;
                ldsm4(aa[mt], slice + OFF_A + arow);
            }
            #pragma unroll
            for (int bt = 0; bt < 4; bt++) {
                uint32_t brow = (uint32_t)((wx * 64 + bt * 16) * ROWB) + laneoff;
                ldsm4(bb[bt], slice + OFF_B + brow);
            }
            #pragma unroll
            for (int mt = 0; mt < 2; mt++)
                #pragma unroll
                for (int bt = 0; bt < 4; bt++) {
                    mma16816(c[mt][bt * 2 + 0], aa[mt], bb[bt][0], bb[bt][2]);
                    mma16816(c[mt][bt * 2 + 1], aa[mt], bb[bt][1], bb[bt][3]);
                }
        }
    }

    // ---------------- Epilogue ----------------
    // Fragment mapping: row gr = i0 + wy*32 + mt*16 + (lane>>2) + 8*(q>>1)
    //                   col gc = j0 + wx*64 + nt*8 + 2*(lane&3) + (q&1)
    float rs[2][2], rm[2][2];
    #pragma unroll
    for (int mt = 0; mt < 2; mt++)
        #pragma unroll
        for (int h = 0; h < 2; h++) { rs[mt][h] = 0.0f; rm[mt][h] = -2.0f; }

    const int lrow0 = wy * 32 + (lane >> 2);       // + mt*16 + 8*(q>>1)
    const int lcol0 = wx * 64 + 2 * (lane & 3);    // + nt*8 + (q&1)

    #pragma unroll
    for (int nt = 0; nt < 8; nt++) {
        float cs0 = 0.0f, cs1 = 0.0f, cm0 = -2.0f, cm1 = -2.0f;
        #pragma unroll
        for (int mt = 0; mt < 2; mt++) {
            #pragma unroll
            for (int q = 0; q < 4; q++) {
                float v = c[mt][nt][q];
                int lr = lrow0 + mt * 16 + 8 * (q >> 1);
                int lc = lcol0 + nt * 8 + (q & 1);
                bool skip = diag && (lc == lr);
                float e = skip ? 0.0f : __expf(fmaf(TAU_INV, v, -TAU_INV));
                rs[mt][q >> 1] += e;
                if (!skip) rm[mt][q >> 1] = fmaxf(rm[mt][q >> 1], v);
                if (q & 1) { cs1 += e; cm1 = fmaxf(cm1, v); }
                else       { cs0 += e; cm0 = fmaxf(cm0, v); }
                if (part && lc == lr) {            // partner pair (one writer each)
                    d_gd[i0 + lr] = v;
                    d_gd[j0 + lc] = v;
                }
            }
        }
        if (!diag) {
            // Column reduction across rows held by other lanes (lane>>2 bits)
            #pragma unroll
            for (int o = 4; o <= 16; o <<= 1) {
                cs0 += __shfl_xor_sync(0xffffffffu, cs0, o);
                cs1 += __shfl_xor_sync(0xffffffffu, cs1, o);
                cm0 = fmaxf(cm0, __shfl_xor_sync(0xffffffffu, cm0, o));
                cm1 = fmaxf(cm1, __shfl_xor_sync(0xffffffffu, cm1, o));
            }
            if ((lane >> 2) == 0) {
                int gc0 = j0 + lcol0 + nt * 8;
                atomicAdd(&d_gsum[gc0],     cs0);
                atomicAdd(&d_gsum[gc0 + 1], cs1);
                if (gc0 < BATCH) {
                    atomicMax(&d_gmax[gc0],     fenc(cm0));
                    atomicMax(&d_gmax[gc0 + 1], fenc(cm1));
                }
            }
        }
    }

    // Row reduction across columns held by other lanes (lane&3 bits)
    #pragma unroll
    for (int mt = 0; mt < 2; mt++) {
        #pragma unroll
        for (int o = 1; o < 4; o <<= 1) {
            rs[mt][0] += __shfl_xor_sync(0xffffffffu, rs[mt][0], o);
            rs[mt][1] += __shfl_xor_sync(0xffffffffu, rs[mt][1], o);
            rm[mt][0] = fmaxf(rm[mt][0], __shfl_xor_sync(0xffffffffu, rm[mt][0], o));
            rm[mt][1] = fmaxf(rm[mt][1], __shfl_xor_sync(0xffffffffu, rm[mt][1], o));
        }
        if ((lane & 3) == 0) {
            int r0 = i0 + lrow0 + mt * 16;
            atomicAdd(&d_gsum[r0],     rs[mt][0]);
            atomicAdd(&d_gsum[r0 + 8], rs[mt][1]);
            if (r0 < BATCH) {
                atomicMax(&d_gmax[r0],     fenc(rm[mt][0]));
                atomicMax(&d_gmax[r0 + 8], fenc(rm[mt][1]));
            }
        }
    }
}

// ---------------------------------------------------------------------------
// Single-block finalize + writeout. Prefetch all loads before dependent math.
__global__ __launch_bounds__(1024) void finalize_kernel(float* out, int out_size) {
    int tid = threadIdx.x;
    float sv[8], dv[8];
    unsigned int mv[4];
    #pragma unroll
    for (int i = 0; i < 8; i++) {
        int r = tid + i * 1024;
        sv[i] = d_gsum[r];
        dv[i] = d_gd[r];
    }
    #pragma unroll
    for (int i = 0; i < 4; i++)
        mv[i] = d_gmax[tid + i * 1024];

    float lossv = 0.0f;
    int corr = 0;
    #pragma unroll
    for (int i = 0; i < 8; i++)
        lossv += (TAU_INV + __logf(sv[i])) - TAU_INV * dv[i];
    #pragma unroll
    for (int i = 0; i < 4; i++)
        corr += (dv[i] >= fdec(mv[i])) ? 1 : 0;  // rows < BATCH only

    #pragma unroll
    for (int o = 16; o > 0; o >>= 1) {
        lossv += __shfl_xor_sync(0xffffffffu, lossv, o);
        corr  += __shfl_xor_sync(0xffffffffu, corr, o);
    }
    __shared__ float sl[32];
    __shared__ int   sc[32];
    int w = tid >> 5, lane = tid & 31;
    if (lane == 0) { sl[w] = lossv; sc[w] = corr; }
    __syncthreads();
    if (tid == 0) {
        float L = 0.0f; int C = 0;
        #pragma unroll
        for (int i = 0; i < 32; i++) { L += sl[i]; C += sc[i]; }
        out[0] = L / (float)NROWS;
        if (out_size > 1)
            out[1] = 100.0f * (float)C / (float)BATCH;
    }
}

// ---------------------------------------------------------------------------
extern "C" void kernel_launch(void* const* d_in, const int* in_sizes, int n_in,
                              void* d_out, int out_size) {
    const float* a = (const float*)d_in[0];
    const float* b = (const float*)d_in[1];
    float* out = (float*)d_out;

    cudaFuncSetAttribute(gram_kernel,
                         cudaFuncAttributeMaxDynamicSharedMemorySize, SMEM_TOTAL);

    norm_kernel<<<NROWS / 8, 256>>>(a, b);
    gram_kernel<<<NBLOCKS, 256, SMEM_TOTAL>>>();
    finalize_kernel<<<1, 1024>>>(out, out_size);
}

// round 13
// speedup vs baseline: 1.1251x; 1.1251x over previous
#include <cuda_runtime.h>
#include <cuda_fp16.h>
#include <math.h>
#include <stdint.h>

#define BATCH   4096
#define NROWS   8192
#define DIM     512
#define TAU_INV 10.0f

// Gram tiling
#define TM 128
#define TN 128
#define KC 32                 // k-chunk (2 k16 slices)
#define NCHUNKS (DIM / KC)    // 16
#define NTILE   (NROWS / TN)  // 64
#define NBLOCKS (NTILE * (NTILE + 1) / 2)   // 2080 upper-triangle tiles
#define NSTAGES 4

// SMEM layout: 32B rows with XOR swizzle (half16 slot h of row r lives at
// r*32 + (h ^ ((r>>2)&1))*16) -> conflict-free ldmatrix with ZERO padding.
#define ROWB   32
#define SLICEB (128 * ROWB)           // 4096
#define MATB   (2 * SLICEB)           // 8192 (2 k16 slices)
#define OFF_A  0
#define OFF_B  MATB
#define STAGEB (2 * MATB)             // 16384
#define SMEM_TOTAL (NSTAGES * STAGEB) // 65536 (< proven-safe 73.7KB)

// ---------------------------------------------------------------------------
// Scratch (device globals: no runtime allocation)
__device__ __half        d_Xh[(size_t)NROWS * DIM];   // 8 MB (L2-resident)
__device__ float         d_gsum[NROWS];
__device__ unsigned int  d_gmax[NROWS];
__device__ float         d_gd[NROWS];

// ---------------------------------------------------------------------------
__device__ __forceinline__ uint32_t smem_to_u32(const void* p) {
    uint32_t a;
    asm("{ .reg .u64 t; cvta.to.shared.u64 t, %1; cvt.u32.u64 %0, t; }"
        : "=r"(a) : "l"(p));
    return a;
}

__device__ __forceinline__ void cp_async16(uint32_t dst, const void* src) {
    asm volatile("cp.async.cg.shared.global [%0], [%1], 16;"
                 :: "r"(dst), "l"(src) : "memory");
}
__device__ __forceinline__ void cp_commit() {
    asm volatile("cp.async.commit_group;" ::: "memory");
}
template <int N>
__device__ __forceinline__ void cp_wait() {
    asm volatile("cp.async.wait_group %0;" :: "n"(N) : "memory");
}

__device__ __forceinline__ void ldsm4(uint32_t* r, uint32_t addr) {
    asm volatile("ldmatrix.sync.aligned.m8n8.x4.shared.b16 {%0,%1,%2,%3}, [%4];"
                 : "=r"(r[0]), "=r"(r[1]), "=r"(r[2]), "=r"(r[3]) : "r"(addr));
}

__device__ __forceinline__ void mma16816(float* d, const uint32_t* a,
                                         uint32_t b0, uint32_t b1) {
    asm volatile(
        "mma.sync.aligned.m16n8k16.row.col.f32.f16.f16.f32 "
        "{%0,%1,%2,%3}, {%4,%5,%6,%7}, {%8,%9}, {%0,%1,%2,%3};\n"
        : "+f"(d[0]), "+f"(d[1]), "+f"(d[2]), "+f"(d[3])
        : "r"(a[0]), "r"(a[1]), "r"(a[2]), "r"(a[3]), "r"(b0), "r"(b1));
}

// Order-preserving float<->uint encoding for atomicMax on float
__device__ __forceinline__ unsigned int fenc(float f) {
    unsigned int u = __float_as_uint(f);
    return (u & 0x80000000u) ? ~u : (u | 0x80000000u);
}
__device__ __forceinline__ float fdec(unsigned int u) {
    u = (u & 0x80000000u) ? (u & 0x7FFFFFFFu) : ~u;
    return __uint_as_float(u);
}

// ---------------------------------------------------------------------------
// Normalize rows -> fp16, warp-per-row (MLP=4, warp-local reduction only).
// Also zeroes the row's accumulators (fused zero).
__global__ __launch_bounds__(256) void norm_kernel(const float* __restrict__ a,
                                                   const float* __restrict__ b) {
    int lane = threadIdx.x & 31;
    int r = blockIdx.x * 8 + (threadIdx.x >> 5);
    const float* src = (r < BATCH) ? a + (size_t)r * DIM
                                   : b + (size_t)(r - BATCH) * DIM;

    if (lane == 0) {
        d_gsum[r] = 0.0f;
        d_gmax[r] = 0u;
        d_gd[r]   = 0.0f;
    }

    // 4 independent float4 loads per lane (coalesced, MLP=4)
    float4 v[4];
    #pragma unroll
    for (int i = 0; i < 4; i++)
        v[i] = reinterpret_cast<const float4*>(src)[lane + 32 * i];

    float ss = 0.0f;
    #pragma unroll
    for (int i = 0; i < 4; i++)
        ss += v[i].x * v[i].x + v[i].y * v[i].y + v[i].z * v[i].z + v[i].w * v[i].w;
    #pragma unroll
    for (int o = 16; o > 0; o >>= 1) ss += __shfl_xor_sync(0xffffffffu, ss, o);

    float scale = 1.0f / fmaxf(sqrtf(ss), 1e-12f);

    uint2* dh = reinterpret_cast<uint2*>(d_Xh + (size_t)r * DIM);
    #pragma unroll
    for (int i = 0; i < 4; i++) {
        __half2 h0 = __floats2half2_rn(v[i].x * scale, v[i].y * scale);
        __half2 h1 = __floats2half2_rn(v[i].z * scale, v[i].w * scale);
        uint2 pk;
        pk.x = *reinterpret_cast<uint32_t*>(&h0);
        pk.y = *reinterpret_cast<uint32_t*>(&h1);
        dh[lane + 32 * i] = pk;
    }
}

// ---------------------------------------------------------------------------
// Gram kernel over the UPPER TRIANGLE of the 64x64 tile grid, single fp16
// MMA chain (fp32 accum), KC=32 with a 4-stage cp.async ring (prefetch
// distance 3, one barrier per chunk), XOR-swizzled 32B rows (64KB smem).
// Off-diagonal tile (bi < bj): row-scan feeds rows i0.., per-COLUMN reduction
// feeds rows j0.. (G symmetric). Diagonal tile: row-scan only, self excluded.
// Partner tiles (bj == bi^32): local diagonal yields d_gd for both rows.
__global__ __launch_bounds__(256, 2) void gram_kernel() {
    extern __shared__ __align__(1024) unsigned char smem[];
    uint32_t sbase = smem_to_u32(smem);

    const int tid  = threadIdx.x;
    const int lane = tid & 31;
    const int wid  = tid >> 5;
    const int wy   = wid & 3;    // M warp (4)
    const int wx   = wid >> 2;   // N warp (2)

    // Linear block id -> (bi, bj) with bi <= bj
    int t = blockIdx.x;
    int bi = (int)((129.0f - sqrtf(16641.0f - 8.0f * (float)t)) * 0.5f);
    if (bi < 0) bi = 0;
    if (bi > NTILE - 1) bi = NTILE - 1;
    while (bi > 0 && bi * NTILE - bi * (bi - 1) / 2 > t) bi--;
    while ((bi + 1) * NTILE - (bi + 1) * bi / 2 <= t) bi++;
    int bj = bi + (t - (bi * NTILE - bi * (bi - 1) / 2));

    const int i0 = bi * TM;
    const int j0 = bj * TN;
    const bool diag = (bi == bj);
    const bool part = (bj == (bi ^ (BATCH / TN)));   // bi<32, bj=bi+32

    float c[2][8][4];
    #pragma unroll
    for (int mt = 0; mt < 2; mt++)
        #pragma unroll
        for (int nt = 0; nt < 8; nt++)
            #pragma unroll
            for (int q = 0; q < 4; q++) c[mt][nt][q] = 0.0f;

    // cp.async loader: one stage = 1024 16B chunks, 4 per thread.
    // idx bits: h=bit0, r=bits1..7, s=bit8, m=bit9 (0=A rows i0.., 1=B rows j0..)
    // Swizzled dst: r*32 + (h ^ ((r>>2)&1))*16
    auto load_stage = [&](int st, int k0) {
        #pragma unroll
        for (int it = 0; it < 4; it++) {
            int idx = tid + it * 256;
            int h = idx & 1;
            int r = (idx >> 1) & 127;
            int s = (idx >> 8) & 1;
            int m = idx >> 9;
            int rowbase = m ? j0 : i0;
            const __half* g =
                d_Xh + (size_t)(rowbase + r) * DIM + k0 + s * 16 + h * 8;
            uint32_t dst = sbase + st * STAGEB + (m ? OFF_B : OFF_A) +
                           s * SLICEB + r * ROWB + ((h ^ ((r >> 2) & 1)) * 16);
            cp_async16(dst, g);
        }
        cp_commit();
    };

    // ldmatrix lane offset with matching swizzle:
    // lrow = (lane&7) + ((lane>>3)&1)*8, half = lane>>4, swbit = (lrow>>2)&1
    const int lrow = (lane & 7) + ((lane >> 3) & 1) * 8;
    const uint32_t laneoff =
        (uint32_t)(lrow * ROWB + (((lane >> 4) ^ ((lrow >> 2) & 1)) * 16));

    // Prologue: three chunks in flight
    load_stage(0, 0);
    load_stage(1, KC);
    load_stage(2, 2 * KC);

    for (int ch = 0; ch < NCHUNKS; ch++) {
        // Drain until chunk ch has landed.
        if (ch + 3 <= NCHUNKS)      cp_wait<2>();
        else if (ch + 2 <= NCHUNKS) cp_wait<1>();
        else                        cp_wait<0>();
        __syncthreads();   // compute of ch-1 done everywhere; stage ch visible

        // Prefetch ch+3 into stage (ch+3)%4 == (ch-1)%4 (consumer confirmed done)
        if (ch + 3 < NCHUNKS) load_stage((ch + 3) & 3, (ch + 3) * KC);

        uint32_t sb = sbase + (ch & 3) * STAGEB;
        #pragma unroll
        for (int s = 0; s < 2; s++) {
            uint32_t slice = sb + s * SLICEB;
            uint32_t aa[2][4], bb[4][4];
            #pragma unroll
            for (int mt = 0; mt < 2; mt++) {
                uint32_t arow = (uint32_t)((wy * 32 + mt * 16) * ROWB) + laneoff;
                ldsm4(aa[mt], slice + OFF_A + arow);
            }
            #pragma unroll
            for (int bt = 0; bt < 4; bt++) {
                uint32_t brow = (uint32_t)((wx * 64 + bt * 16) * ROWB) + laneoff;
                ldsm4(bb[bt], slice + OFF_B + brow);
            }
            #pragma unroll
            for (int mt = 0; mt < 2; mt++)
                #pragma unroll
                for (int bt = 0; bt < 4; bt++) {
                    mma16816(c[mt][bt * 2 + 0], aa[mt], bb[bt][0], bb[bt][2]);
                    mma16816(c[mt][bt * 2 + 1], aa[mt], bb[bt][1], bb[bt][3]);
                }
        }
    }

    // ---------------- Epilogue ----------------
    // Fragment mapping: row gr = i0 + wy*32 + mt*16 + (lane>>2) + 8*(q>>1)
    //                   col gc = j0 + wx*64 + nt*8 + 2*(lane&3) + (q&1)
    float rs[2][2], rm[2][2];
    #pragma unroll
    for (int mt = 0; mt < 2; mt++)
        #pragma unroll
        for (int h = 0; h < 2; h++) { rs[mt][h] = 0.0f; rm[mt][h] = -2.0f; }

    const int lrow0 = wy * 32 + (lane >> 2);       // + mt*16 + 8*(q>>1)
    const int lcol0 = wx * 64 + 2 * (lane & 3);    // + nt*8 + (q&1)

    #pragma unroll
    for (int nt = 0; nt < 8; nt++) {
        float cs0 = 0.0f, cs1 = 0.0f, cm0 = -2.0f, cm1 = -2.0f;
        #pragma unroll
        for (int mt = 0; mt < 2; mt++) {
            #pragma unroll
            for (int q = 0; q < 4; q++) {
                float v = c[mt][nt][q];
                int lr = lrow0 + mt * 16 + 8 * (q >> 1);
                int lc = lcol0 + nt * 8 + (q & 1);
                bool skip = diag && (lc == lr);
                float e = skip ? 0.0f : __expf(fmaf(TAU_INV, v, -TAU_INV));
                rs[mt][q >> 1] += e;
                if (!skip) rm[mt][q >> 1] = fmaxf(rm[mt][q >> 1], v);
                if (q & 1) { cs1 += e; cm1 = fmaxf(cm1, v); }
                else       { cs0 += e; cm0 = fmaxf(cm0, v); }
                if (part && lc == lr) {            // partner pair (one writer each)
                    d_gd[i0 + lr] = v;
                    d_gd[j0 + lc] = v;
                }
            }
        }
        if (!diag) {
            // Column reduction across rows held by other lanes (lane>>2 bits)
            #pragma unroll
            for (int o = 4; o <= 16; o <<= 1) {
                cs0 += __shfl_xor_sync(0xffffffffu, cs0, o);
                cs1 += __shfl_xor_sync(0xffffffffu, cs1, o);
                cm0 = fmaxf(cm0, __shfl_xor_sync(0xffffffffu, cm0, o));
                cm1 = fmaxf(cm1, __shfl_xor_sync(0xffffffffu, cm1, o));
            }
            if ((lane >> 2) == 0) {
                int gc0 = j0 + lcol0 + nt * 8;
                atomicAdd(&d_gsum[gc0],     cs0);
                atomicAdd(&d_gsum[gc0 + 1], cs1);
                if (gc0 < BATCH) {
                    atomicMax(&d_gmax[gc0],     fenc(cm0));
                    atomicMax(&d_gmax[gc0 + 1], fenc(cm1));
                }
            }
        }
    }

    // Row reduction across columns held by other lanes (lane&3 bits)
    #pragma unroll
    for (int mt = 0; mt < 2; mt++) {
        #pragma unroll
        for (int o = 1; o < 4; o <<= 1) {
            rs[mt][0] += __shfl_xor_sync(0xffffffffu, rs[mt][0], o);
            rs[mt][1] += __shfl_xor_sync(0xffffffffu, rs[mt][1], o);
            rm[mt][0] = fmaxf(rm[mt][0], __shfl_xor_sync(0xffffffffu, rm[mt][0], o));
            rm[mt][1] = fmaxf(rm[mt][1], __shfl_xor_sync(0xffffffffu, rm[mt][1], o));
        }
        if ((lane & 3) == 0) {
            int r0 = i0 + lrow0 + mt * 16;
            atomicAdd(&d_gsum[r0],     rs[mt][0]);
            atomicAdd(&d_gsum[r0 + 8], rs[mt][1]);
            if (r0 < BATCH) {
                atomicMax(&d_gmax[r0],     fenc(rm[mt][0]));
                atomicMax(&d_gmax[r0 + 8], fenc(rm[mt][1]));
            }
        }
    }
}

// ---------------------------------------------------------------------------
// Single-block finalize + writeout. Prefetch all loads before dependent math.
__global__ __launch_bounds__(1024) void finalize_kernel(float* out, int out_size) {
    int tid = threadIdx.x;
    float sv[8], dv[8];
    unsigned int mv[4];
    #pragma unroll
    for (int i = 0; i < 8; i++) {
        int r = tid + i * 1024;
        sv[i] = d_gsum[r];
        dv[i] = d_gd[r];
    }
    #pragma unroll
    for (int i = 0; i < 4; i++)
        mv[i] = d_gmax[tid + i * 1024];

    float lossv = 0.0f;
    int corr = 0;
    #pragma unroll
    for (int i = 0; i < 8; i++)
        lossv += (TAU_INV + __logf(sv[i])) - TAU_INV * dv[i];
    #pragma unroll
    for (int i = 0; i < 4; i++)
        corr += (dv[i] >= fdec(mv[i])) ? 1 : 0;  // rows < BATCH only

    #pragma unroll
    for (int o = 16; o > 0; o >>= 1) {
        lossv += __shfl_xor_sync(0xffffffffu, lossv, o);
        corr  += __shfl_xor_sync(0xffffffffu, corr, o);
    }
    __shared__ float sl[32];
    __shared__ int   sc[32];
    int w = tid >> 5, lane = tid & 31;
    if (lane == 0) { sl[w] = lossv; sc[w] = corr; }
    __syncthreads();
    if (tid == 0) {
        float L = 0.0f; int C = 0;
        #pragma unroll
        for (int i = 0; i < 32; i++) { L += sl[i]; C += sc[i]; }
        out[0] = L / (float)NROWS;
        if (out_size > 1)
            out[1] = 100.0f * (float)C / (float)BATCH;
    }
}

// ---------------------------------------------------------------------------
extern "C" void kernel_launch(void* const* d_in, const int* in_sizes, int n_in,
                              void* d_out, int out_size) {
    const float* a = (const float*)d_in[0];
    const float* b = (const float*)d_in[1];
    float* out = (float*)d_out;

    cudaFuncSetAttribute(gram_kernel,
                         cudaFuncAttributeMaxDynamicSharedMemorySize, SMEM_TOTAL);

    norm_kernel<<<NROWS / 8, 256>>>(a, b);
    gram_kernel<<<NBLOCKS, 256, SMEM_TOTAL>>>();
    finalize_kernel<<<1, 1024>>>(out, out_size);
}

// round 14
// speedup vs baseline: 1.3415x; 1.1923x over previous
#include <cuda_runtime.h>
#include <cuda_fp16.h>
#include <math.h>
#include <stdint.h>

#define BATCH   4096
#define NROWS   8192
#define DIM     512
#define TAU_INV 10.0f

// Gram tiling
#define TM 128
#define TN 128
#define KC 32                 // k-chunk (2 k16 slices)
#define NCHUNKS (DIM / KC)    // 16
#define NTILE   (NROWS / TN)  // 64
#define NBLOCKS (NTILE * (NTILE + 1) / 2)   // 2080 upper-triangle tiles
#define NSTAGES 3             // R8-proven: prefetch distance 2

// SMEM layout: 32B rows with XOR swizzle (half16 slot h of row r lives at
// r*32 + (h ^ ((r>>2)&1))*16) -> conflict-free ldmatrix with ZERO padding.
#define ROWB   32
#define SLICEB (128 * ROWB)           // 4096
#define MATB   (2 * SLICEB)           // 8192 (2 k16 slices)
#define OFF_A  0
#define OFF_B  MATB
#define STAGEB (2 * MATB)             // 16384
#define SMEM_TOTAL (NSTAGES * STAGEB) // 49152

// ---------------------------------------------------------------------------
// Scratch (device globals: no runtime allocation)
__device__ __half        d_Xh[(size_t)NROWS * DIM];   // 8 MB (L2-resident)
__device__ float         d_gsum[NROWS];
__device__ unsigned int  d_gmax[NROWS];
__device__ float         d_gd[NROWS];

// ---------------------------------------------------------------------------
__device__ __forceinline__ uint32_t smem_to_u32(const void* p) {
    uint32_t a;
    asm("{ .reg .u64 t; cvta.to.shared.u64 t, %1; cvt.u32.u64 %0, t; }"
        : "=r"(a) : "l"(p));
    return a;
}

__device__ __forceinline__ void cp_async16(uint32_t dst, const void* src) {
    asm volatile("cp.async.cg.shared.global [%0], [%1], 16;"
                 :: "r"(dst), "l"(src) : "memory");
}
__device__ __forceinline__ void cp_commit() {
    asm volatile("cp.async.commit_group;" ::: "memory");
}
template <int N>
__device__ __forceinline__ void cp_wait() {
    asm volatile("cp.async.wait_group %0;" :: "n"(N) : "memory");
}

__device__ __forceinline__ void ldsm4(uint32_t* r, uint32_t addr) {
    asm volatile("ldmatrix.sync.aligned.m8n8.x4.shared.b16 {%0,%1,%2,%3}, [%4];"
                 : "=r"(r[0]), "=r"(r[1]), "=r"(r[2]), "=r"(r[3]) : "r"(addr));
}

__device__ __forceinline__ void mma16816(float* d, const uint32_t* a,
                                         uint32_t b0, uint32_t b1) {
    asm volatile(
        "mma.sync.aligned.m16n8k16.row.col.f32.f16.f16.f32 "
        "{%0,%1,%2,%3}, {%4,%5,%6,%7}, {%8,%9}, {%0,%1,%2,%3};\n"
        : "+f"(d[0]), "+f"(d[1]), "+f"(d[2]), "+f"(d[3])
        : "r"(a[0]), "r"(a[1]), "r"(a[2]), "r"(a[3]), "r"(b0), "r"(b1));
}

// Order-preserving float<->uint encoding for atomicMax on float
__device__ __forceinline__ unsigned int fenc(float f) {
    unsigned int u = __float_as_uint(f);
    return (u & 0x80000000u) ? ~u : (u | 0x80000000u);
}
__device__ __forceinline__ float fdec(unsigned int u) {
    u = (u & 0x80000000u) ? (u & 0x7FFFFFFFu) : ~u;
    return __uint_as_float(u);
}

// ---------------------------------------------------------------------------
// Normalize rows -> fp16, warp-per-row (MLP=4, warp-local reduction only).
// Also zeroes the row's accumulators (fused zero).
__global__ __launch_bounds__(256) void norm_kernel(const float* __restrict__ a,
                                                   const float* __restrict__ b) {
    int lane = threadIdx.x & 31;
    int r = blockIdx.x * 8 + (threadIdx.x >> 5);
    const float* src = (r < BATCH) ? a + (size_t)r * DIM
                                   : b + (size_t)(r - BATCH) * DIM;

    if (lane == 0) {
        d_gsum[r] = 0.0f;
        d_gmax[r] = 0u;
        d_gd[r]   = 0.0f;
    }

    // 4 independent float4 loads per lane (coalesced, MLP=4)
    float4 v[4];
    #pragma unroll
    for (int i = 0; i < 4; i++)
        v[i] = reinterpret_cast<const float4*>(src)[lane + 32 * i];

    float ss = 0.0f;
    #pragma unroll
    for (int i = 0; i < 4; i++)
        ss += v[i].x * v[i].x + v[i].y * v[i].y + v[i].z * v[i].z + v[i].w * v[i].w;
    #pragma unroll
    for (int o = 16; o > 0; o >>= 1) ss += __shfl_xor_sync(0xffffffffu, ss, o);

    float scale = 1.0f / fmaxf(sqrtf(ss), 1e-12f);

    uint2* dh = reinterpret_cast<uint2*>(d_Xh + (size_t)r * DIM);
    #pragma unroll
    for (int i = 0; i < 4; i++) {
        __half2 h0 = __floats2half2_rn(v[i].x * scale, v[i].y * scale);
        __half2 h1 = __floats2half2_rn(v[i].z * scale, v[i].w * scale);
        uint2 pk;
        pk.x = *reinterpret_cast<uint32_t*>(&h0);
        pk.y = *reinterpret_cast<uint32_t*>(&h1);
        dh[lane + 32 * i] = pk;
    }
}

// ---------------------------------------------------------------------------
// Gram kernel over the UPPER TRIANGLE of the 64x64 tile grid, single fp16
// MMA chain (fp32 accum). R8-proven pipeline: KC=32, 3-stage cp.async ring,
// prefetch distance 2, one barrier per chunk. XOR-swizzled 32B rows (48KB).
// Off-diagonal tile (bi < bj): row-scan feeds rows i0.., per-COLUMN reduction
// feeds rows j0.. (G symmetric). Diagonal tile: row-scan only, self excluded.
// Partner tiles (bj == bi^32): local diagonal yields d_gd for both rows.
__global__ __launch_bounds__(256, 2) void gram_kernel() {
    extern __shared__ __align__(1024) unsigned char smem[];
    uint32_t sbase = smem_to_u32(smem);

    const int tid  = threadIdx.x;
    const int lane = tid & 31;
    const int wid  = tid >> 5;
    const int wy   = wid & 3;    // M warp (4)
    const int wx   = wid >> 2;   // N warp (2)

    // Linear block id -> (bi, bj) with bi <= bj
    int t = blockIdx.x;
    int bi = (int)((129.0f - sqrtf(16641.0f - 8.0f * (float)t)) * 0.5f);
    if (bi < 0) bi = 0;
    if (bi > NTILE - 1) bi = NTILE - 1;
    while (bi > 0 && bi * NTILE - bi * (bi - 1) / 2 > t) bi--;
    while ((bi + 1) * NTILE - (bi + 1) * bi / 2 <= t) bi++;
    int bj = bi + (t - (bi * NTILE - bi * (bi - 1) / 2));

    const int i0 = bi * TM;
    const int j0 = bj * TN;
    const bool diag = (bi == bj);
    const bool part = (bj == (bi ^ (BATCH / TN)));   // bi<32, bj=bi+32

    float c[2][8][4];
    #pragma unroll
    for (int mt = 0; mt < 2; mt++)
        #pragma unroll
        for (int nt = 0; nt < 8; nt++)
            #pragma unroll
            for (int q = 0; q < 4; q++) c[mt][nt][q] = 0.0f;

    // cp.async loader: one stage = 1024 16B chunks, 4 per thread.
    // idx bits: h=bit0, r=bits1..7, s=bit8, m=bit9 (0=A rows i0.., 1=B rows j0..)
    // Swizzled dst: r*32 + (h ^ ((r>>2)&1))*16
    auto load_stage = [&](int st, int k0) {
        #pragma unroll
        for (int it = 0; it < 4; it++) {
            int idx = tid + it * 256;
            int h = idx & 1;
            int r = (idx >> 1) & 127;
            int s = (idx >> 8) & 1;
            int m = idx >> 9;
            int rowbase = m ? j0 : i0;
            const __half* g =
                d_Xh + (size_t)(rowbase + r) * DIM + k0 + s * 16 + h * 8;
            uint32_t dst = sbase + st * STAGEB + (m ? OFF_B : OFF_A) +
                           s * SLICEB + r * ROWB + ((h ^ ((r >> 2) & 1)) * 16);
            cp_async16(dst, g);
        }
        cp_commit();
    };

    // ldmatrix lane offset with matching swizzle:
    // lrow = (lane&7) + ((lane>>3)&1)*8, half = lane>>4, swbit = (lrow>>2)&1
    const int lrow = (lane & 7) + ((lane >> 3) & 1) * 8;
    const uint32_t laneoff =
        (uint32_t)(lrow * ROWB + (((lane >> 4) ^ ((lrow >> 2) & 1)) * 16));

    // Prologue: two chunks in flight (R8-proven prefetch distance)
    load_stage(0, 0);
    load_stage(1, KC);

    for (int ch = 0; ch < NCHUNKS; ch++) {
        // Ensure chunk ch's data has landed (FIFO: <=1 pending leaves ch+1 only)
        if (ch + 2 < NCHUNKS) cp_wait<1>(); else cp_wait<0>();
        __syncthreads();   // all warps done with stage (ch-1)%3; ch%3 visible

        if (ch + 2 < NCHUNKS) load_stage((ch + 2) % NSTAGES, (ch + 2) * KC);

        uint32_t sb = sbase + (ch % NSTAGES) * STAGEB;
        #pragma unroll
        for (int s = 0; s < 2; s++) {
            uint32_t slice = sb + s * SLICEB;
            uint32_t aa[2][4], bb[4][4];
            #pragma unroll
            for (int mt = 0; mt < 2; mt++) {
                uint32_t arow = (uint32_t)((wy * 32 + mt * 16) * ROWB) + laneoff;
                ldsm4(aa[mt], slice + OFF_A + arow);
            }
            #pragma unroll
            for (int bt = 0; bt < 4; bt++) {
                uint32_t brow = (uint32_t)((wx * 64 + bt * 16) * ROWB) + laneoff;
                ldsm4(bb[bt], slice + OFF_B + brow);
            }
            #pragma unroll
            for (int mt = 0; mt < 2; mt++)
                #pragma unroll
                for (int bt = 0; bt < 4; bt++) {
                    mma16816(c[mt][bt * 2 + 0], aa[mt], bb[bt][0], bb[bt][2]);
                    mma16816(c[mt][bt * 2 + 1], aa[mt], bb[bt][1], bb[bt][3]);
                }
        }
    }

    // ---------------- Epilogue ----------------
    // Fragment mapping: row gr = i0 + wy*32 + mt*16 + (lane>>2) + 8*(q>>1)
    //                   col gc = j0 + wx*64 + nt*8 + 2*(lane&3) + (q&1)
    float rs[2][2], rm[2][2];
    #pragma unroll
    for (int mt = 0; mt < 2; mt++)
        #pragma unroll
        for (int h = 0; h < 2; h++) { rs[mt][h] = 0.0f; rm[mt][h] = -2.0f; }

    const int lrow0 = wy * 32 + (lane >> 2);       // + mt*16 + 8*(q>>1)
    const int lcol0 = wx * 64 + 2 * (lane & 3);    // + nt*8 + (q&1)

    #pragma unroll
    for (int nt = 0; nt < 8; nt++) {
        float cs0 = 0.0f, cs1 = 0.0f, cm0 = -2.0f, cm1 = -2.0f;
        #pragma unroll
        for (int mt = 0; mt < 2; mt++) {
            #pragma unroll
            for (int q = 0; q < 4; q++) {
                float v = c[mt][nt][q];
                int lr = lrow0 + mt * 16 + 8 * (q >> 1);
                int lc = lcol0 + nt * 8 + (q & 1);
                bool skip = diag && (lc == lr);
                float e = skip ? 0.0f : __expf(fmaf(TAU_INV, v, -TAU_INV));
                rs[mt][q >> 1] += e;
                if (!skip) rm[mt][q >> 1] = fmaxf(rm[mt][q >> 1], v);
                if (q & 1) { cs1 += e; cm1 = fmaxf(cm1, v); }
                else       { cs0 += e; cm0 = fmaxf(cm0, v); }
                if (part && lc == lr) {            // partner pair (one writer each)
                    d_gd[i0 + lr] = v;
                    d_gd[j0 + lc] = v;
                }
            }
        }
        if (!diag) {
            // Column reduction across rows held by other lanes (lane>>2 bits)
            #pragma unroll
            for (int o = 4; o <= 16; o <<= 1) {
                cs0 += __shfl_xor_sync(0xffffffffu, cs0, o);
                cs1 += __shfl_xor_sync(0xffffffffu, cs1, o);
                cm0 = fmaxf(cm0, __shfl_xor_sync(0xffffffffu, cm0, o));
                cm1 = fmaxf(cm1, __shfl_xor_sync(0xffffffffu, cm1, o));
            }
            if ((lane >> 2) == 0) {
                int gc0 = j0 + lcol0 + nt * 8;
                atomicAdd(&d_gsum[gc0],     cs0);
                atomicAdd(&d_gsum[gc0 + 1], cs1);
                if (gc0 < BATCH) {
                    atomicMax(&d_gmax[gc0],     fenc(cm0));
                    atomicMax(&d_gmax[gc0 + 1], fenc(cm1));
                }
            }
        }
    }

    // Row reduction across columns held by other lanes (lane&3 bits)
    #pragma unroll
    for (int mt = 0; mt < 2; mt++) {
        #pragma unroll
        for (int o = 1; o < 4; o <<= 1) {
            rs[mt][0] += __shfl_xor_sync(0xffffffffu, rs[mt][0], o);
            rs[mt][1] += __shfl_xor_sync(0xffffffffu, rs[mt][1], o);
            rm[mt][0] = fmaxf(rm[mt][0], __shfl_xor_sync(0xffffffffu, rm[mt][0], o));
            rm[mt][1] = fmaxf(rm[mt][1], __shfl_xor_sync(0xffffffffu, rm[mt][1], o));
        }
        if ((lane & 3) == 0) {
            int r0 = i0 + lrow0 + mt * 16;
            atomicAdd(&d_gsum[r0],     rs[mt][0]);
            atomicAdd(&d_gsum[r0 + 8], rs[mt][1]);
            if (r0 < BATCH) {
                atomicMax(&d_gmax[r0],     fenc(rm[mt][0]));
                atomicMax(&d_gmax[r0 + 8], fenc(rm[mt][1]));
            }
        }
    }
}

// ---------------------------------------------------------------------------
// Single-block finalize + writeout. Prefetch all loads before dependent math.
__global__ __launch_bounds__(1024) void finalize_kernel(float* out, int out_size) {
    int tid = threadIdx.x;
    float sv[8], dv[8];
    unsigned int mv[4];
    #pragma unroll
    for (int i = 0; i < 8; i++) {
        int r = tid + i * 1024;
        sv[i] = d_gsum[r];
        dv[i] = d_gd[r];
    }
    #pragma unroll
    for (int i = 0; i < 4; i++)
        mv[i] = d_gmax[tid + i * 1024];

    float lossv = 0.0f;
    int corr = 0;
    #pragma unroll
    for (int i = 0; i < 8; i++)
        lossv += (TAU_INV + __logf(sv[i])) - TAU_INV * dv[i];
    #pragma unroll
    for (int i = 0; i < 4; i++)
        corr += (dv[i] >= fdec(mv[i])) ? 1 : 0;  // rows < BATCH only

    #pragma unroll
    for (int o = 16; o > 0; o >>= 1) {
        lossv += __shfl_xor_sync(0xffffffffu, lossv, o);
        corr  += __shfl_xor_sync(0xffffffffu, corr, o);
    }
    __shared__ float sl[32];
    __shared__ int   sc[32];
    int w = tid >> 5, lane = tid & 31;
    if (lane == 0) { sl[w] = lossv; sc[w] = corr; }
    __syncthreads();
    if (tid == 0) {
        float L = 0.0f; int C = 0;
        #pragma unroll
        for (int i = 0; i < 32; i++) { L += sl[i]; C += sc[i]; }
        out[0] = L / (float)NROWS;
        if (out_size > 1)
            out[1] = 100.0f * (float)C / (float)BATCH;
    }
}

// ---------------------------------------------------------------------------
extern "C" void kernel_launch(void* const* d_in, const int* in_sizes, int n_in,
                              void* d_out, int out_size) {
    const float* a = (const float*)d_in[0];
    const float* b = (const float*)d_in[1];
    float* out = (float*)d_out;

    cudaFuncSetAttribute(gram_kernel,
                         cudaFuncAttributeMaxDynamicSharedMemorySize, SMEM_TOTAL);

    norm_kernel<<<NROWS / 8, 256>>>(a, b);
    gram_kernel<<<NBLOCKS, 256, SMEM_TOTAL>>>();
    finalize_kernel<<<1, 1024>>>(out, out_size);
}